// round 1
// baseline (speedup 1.0000x reference)
#include <cuda_runtime.h>
#include <cuda_bf16.h>

// Block-diagonal GEMM baseline (fp32 FFMA, register-blocked SGEMM).
// x:      [tokens=16384, H=4096] fp32 (row-major), logical [tokens, 8, 512]
// blocks: [8, 512, 512] fp32 (row-major)
// out[n, k*512+c] = sum_b x[n, k*512+b] * blocks[k, b, c]
//
// Per k-block GEMM: A [M x 512] lda=4096, B [512 x 512] ldb=512,
// C [M x 512] ldc=4096 (column offset k*512).

#define HIDDEN   4096
#define BLOCKDIM 512
#define NBLOCKS  8

#define BM 128
#define BN 128
#define BK 8
#define TM 8
#define TN 8
#define NTHREADS 256  // (BM/TM)*(BN/TN)

__global__ __launch_bounds__(NTHREADS, 2)
void tptrans_sgemm_kernel(const float* __restrict__ x,
                          const float* __restrict__ w,
                          float* __restrict__ out,
                          int M)
{
    const int kb = blockIdx.z;                 // which 512x512 block
    const int rowBase = blockIdx.x * BM;       // token tile
    const int colBase = blockIdx.y * BN;       // output-col tile within block

    const float* A = x   + (size_t)kb * BLOCKDIM;                    // row stride HIDDEN
    const float* B = w   + (size_t)kb * BLOCKDIM * BLOCKDIM;         // row-major 512x512
    float*       C = out + (size_t)kb * BLOCKDIM;                    // row stride HIDDEN

    __shared__ float As[BK][BM];   // A tile, transposed (K-major -> M contiguous)
    __shared__ float Bs[BK][BN];

    const int tid = threadIdx.x;

    // A tile load mapping: 128 rows x 8 cols = 1024 floats = 256 x float4
    //  2 float4 per row of the tile
    const int aRow = tid >> 1;          // 0..127
    const int aCol = (tid & 1) * 4;     // 0 or 4

    // B tile load mapping: 8 rows x 128 cols = 1024 floats = 256 x float4
    const int bRow = tid >> 5;          // 0..7
    const int bCol = (tid & 31) * 4;    // 0..124

    // Compute mapping: 16x16 thread grid, each does 8x8
    const int threadRow = (tid >> 4) * TM;  // 0..120
    const int threadCol = (tid & 15) * TN;  // 0..120

    float acc[TM][TN];
    #pragma unroll
    for (int i = 0; i < TM; i++)
        #pragma unroll
        for (int j = 0; j < TN; j++)
            acc[i][j] = 0.0f;

    const int numKTiles = BLOCKDIM / BK;  // 64

    for (int kt = 0; kt < numKTiles; kt++) {
        // Load A tile (transposed into smem)
        {
            const float* src = A + (size_t)(rowBase + aRow) * HIDDEN + kt * BK + aCol;
            float4 v = *reinterpret_cast<const float4*>(src);
            As[aCol + 0][aRow] = v.x;
            As[aCol + 1][aRow] = v.y;
            As[aCol + 2][aRow] = v.z;
            As[aCol + 3][aRow] = v.w;
        }
        // Load B tile
        {
            const float* src = B + (size_t)(kt * BK + bRow) * BLOCKDIM + colBase + bCol;
            float4 v = *reinterpret_cast<const float4*>(src);
            *reinterpret_cast<float4*>(&Bs[bRow][bCol]) = v;
        }
        __syncthreads();

        #pragma unroll
        for (int kk = 0; kk < BK; kk++) {
            float regA[TM], regB[TN];
            #pragma unroll
            for (int i = 0; i < TM; i++) regA[i] = As[kk][threadRow + i];
            #pragma unroll
            for (int j = 0; j < TN; j++) regB[j] = Bs[kk][threadCol + j];
            #pragma unroll
            for (int i = 0; i < TM; i++)
                #pragma unroll
                for (int j = 0; j < TN; j++)
                    acc[i][j] = fmaf(regA[i], regB[j], acc[i][j]);
        }
        __syncthreads();
    }

    // Write out: 8 rows x 8 cols per thread, 2x float4 per row
    #pragma unroll
    for (int i = 0; i < TM; i++) {
        float* dst = C + (size_t)(rowBase + threadRow + i) * HIDDEN + colBase + threadCol;
        float4 v0 = make_float4(acc[i][0], acc[i][1], acc[i][2], acc[i][3]);
        float4 v1 = make_float4(acc[i][4], acc[i][5], acc[i][6], acc[i][7]);
        *reinterpret_cast<float4*>(dst)     = v0;
        *reinterpret_cast<float4*>(dst + 4) = v1;
    }
}

extern "C" void kernel_launch(void* const* d_in, const int* in_sizes, int n_in,
                              void* d_out, int out_size)
{
    const float* x      = (const float*)d_in[0];   // [tokens, 4096]
    const float* blocks = (const float*)d_in[1];   // [8, 512, 512]
    float*       out    = (float*)d_out;

    const int M = in_sizes[0] / HIDDEN;            // 16384 tokens

    dim3 grid(M / BM, BLOCKDIM / BN, NBLOCKS);     // (128, 4, 8)
    dim3 block(NTHREADS);
    tptrans_sgemm_kernel<<<grid, block>>>(x, blocks, out, M);
}

// round 3
// speedup vs baseline: 6.1279x; 6.1279x over previous
#include <cuda_runtime.h>
#include <cstdint>

// Block-diagonal GEMM via mma.sync tf32 (sm_80-class PTX — no 'a'-target features).
// x:      [16384, 4096] fp32, logical [tokens, 8, 512]
// blocks: [8, 512, 512] fp32 row-major ([k][n] per block)
// out[m, kb*512+n] = sum_k x[m, kb*512+k] * blocks[kb, k, n]

#define HIDDEN 4096
#define BLKD   512
#define NB     8
#define BM     128
#define BN     128
#define BK     32            // 32 tf32 = 128 B per smem row
#define NITER  (BLKD / BK)   // 16
#define NTH    256

#define ABYTES (BM * BK * 4)             // 16384
#define BBYTES (BN * BK * 4)             // 16384
#define BUFBYTES (ABYTES + BBYTES)       // 32768
#define SMEM_BYTES (2 * BUFBYTES)        // 65536

// Transposed + tf32(rna)-rounded blocks: bt[kb][n][k]
__device__ float g_bt[NB * BLKD * BLKD];

#define SWZ(o) ((o) ^ (((o) >> 3) & 0x70))

static __device__ __forceinline__ uint32_t smem_u32(const void* p) {
    uint32_t a;
    asm("{ .reg .u64 t; cvta.to.shared.u64 t, %1; cvt.u32.u64 %0, t; }"
        : "=r"(a) : "l"(p));
    return a;
}
static __device__ __forceinline__ uint32_t f2tf32(float f) {
    uint32_t r;
    asm("cvt.rna.tf32.f32 %0, %1;" : "=r"(r) : "f"(f));
    return r;
}

#define LDSM4(r0, r1, r2, r3, addr)                                          \
    asm volatile("ldmatrix.sync.aligned.m8n8.x4.shared.b16 {%0,%1,%2,%3}, [%4];" \
                 : "=r"(r0), "=r"(r1), "=r"(r2), "=r"(r3) : "r"(addr))

#define MMA_TF32(c, a, b)                                                    \
    asm volatile("mma.sync.aligned.m16n8k8.row.col.f32.tf32.tf32.f32 "       \
                 "{%0,%1,%2,%3}, {%4,%5,%6,%7}, {%8,%9}, {%0,%1,%2,%3};"     \
                 : "+f"((c)[0]), "+f"((c)[1]), "+f"((c)[2]), "+f"((c)[3])    \
                 : "r"((a)[0]), "r"((a)[1]), "r"((a)[2]), "r"((a)[3]),       \
                   "r"((b)[0]), "r"((b)[1]))

#define CPASYNC16(dst, src)                                                  \
    asm volatile("cp.async.cg.shared.global [%0], [%1], 16;"                 \
                 :: "r"(dst), "l"(src) : "memory")

// ---------------- pre-pass: transpose + tf32-round blocks ----------------
__global__ void prep_b_kernel(const float* __restrict__ blocks) {
    __shared__ float tile[32][33];
    const int kb = blockIdx.z;
    const int k0 = blockIdx.x * 32, n0 = blockIdx.y * 32;
    const int tx = threadIdx.x, ty = threadIdx.y;  // 32 x 8
    #pragma unroll
    for (int i = 0; i < 32; i += 8)
        tile[ty + i][tx] = blocks[(size_t)kb * BLKD * BLKD + (size_t)(k0 + ty + i) * BLKD + n0 + tx];
    __syncthreads();
    uint32_t* bt = reinterpret_cast<uint32_t*>(g_bt);
    #pragma unroll
    for (int i = 0; i < 32; i += 8)
        bt[(size_t)kb * BLKD * BLKD + (size_t)(n0 + ty + i) * BLKD + k0 + tx] =
            f2tf32(tile[tx][ty + i]);
}

// ---------------- main GEMM ----------------
__global__ __launch_bounds__(NTH)
void tpt_mma_kernel(const float* __restrict__ x, float* __restrict__ out) {
    extern __shared__ __align__(1024) char smem[];
    const uint32_t sbase = smem_u32(smem);

    const int kb = blockIdx.z;
    const int m0 = blockIdx.x * BM;
    const int n0 = blockIdx.y * BN;
    const int tid = threadIdx.x;
    const int wid = tid >> 5, l = tid & 31;
    const int wm0 = (wid & 1) * 64;   // warp M offset within tile
    const int wn0 = (wid >> 1) * 32;  // warp N offset within tile

    // staging map: thread -> (row rbase+32i, 16B-chunk q), i = 0..3
    const int q = tid & 7;
    const int rbase = tid >> 3;  // 0..31
    const uint32_t stg_swz = SWZ((uint32_t)(rbase * 128 + q * 16));  // +i*4096 safe

    const float* Ag = x + (size_t)(m0 + rbase) * HIDDEN + kb * BLKD + q * 4;
    const float* Bg = g_bt + (size_t)kb * BLKD * BLKD + (size_t)(n0 + rbase) * BLKD + q * 4;

    float acc[4][4][4];
    #pragma unroll
    for (int mi = 0; mi < 4; mi++)
        #pragma unroll
        for (int nt = 0; nt < 4; nt++)
            #pragma unroll
            for (int r = 0; r < 4; r++) acc[mi][nt][r] = 0.0f;

    // ldmatrix per-lane address components
    const int mat = l >> 3;          // 0..3
    const int r8  = l & 7;
    // A: mat0 rows+0 col+0 | mat1 rows+8 col+0 | mat2 rows+0 col+16 | mat3 rows+8 col+16
    const int a_rowadd = (mat & 1) * 8 + r8;
    const int a_colb   = (mat >> 1) * 16;
    // B: mat0 n+0 col+0 | mat1 n+0 col+16 | mat2 n+8 col+0 | mat3 n+8 col+16
    const int b_rowadd = (mat >> 1) * 8 + r8;
    const int b_colb   = (mat & 1) * 16;

    float4 ra[4];

    // ---- prologue: B(0) via cp.async into buf0, A(0) into regs ----
    {
        const uint32_t bdst = sbase + ABYTES + stg_swz;
        #pragma unroll
        for (int i = 0; i < 4; i++)
            CPASYNC16(bdst + i * 4096u, Bg + (size_t)i * 32 * BLKD);
        asm volatile("cp.async.commit_group;" ::: "memory");
        #pragma unroll
        for (int i = 0; i < 4; i++)
            ra[i] = *reinterpret_cast<const float4*>(Ag + (size_t)i * 32 * HIDDEN);
    }

    #pragma unroll 1
    for (int kt = 0; kt < NITER; kt++) {
        const uint32_t buf = (uint32_t)(kt & 1) * BUFBYTES;
        if (kt > 0) __syncthreads();  // all compute(kt-1) done before writes below

        // STS A(kt) with rna tf32 rounding
        {
            const uint32_t adst = sbase + buf + stg_swz;
            #pragma unroll
            for (int i = 0; i < 4; i++) {
                uint32_t v0 = f2tf32(ra[i].x), v1 = f2tf32(ra[i].y),
                         v2 = f2tf32(ra[i].z), v3 = f2tf32(ra[i].w);
                asm volatile("st.shared.v4.b32 [%0], {%1,%2,%3,%4};"
                             :: "r"(adst + (uint32_t)i * 4096u),
                                "r"(v0), "r"(v1), "r"(v2), "r"(v3) : "memory");
            }
        }

        if (kt + 1 < NITER) {
            // cp.async B(kt+1) into other buffer
            const uint32_t bdst = sbase + (BUFBYTES - buf) + ABYTES + stg_swz;
            const float* bsrc = Bg + (size_t)(kt + 1) * BK;
            #pragma unroll
            for (int i = 0; i < 4; i++)
                CPASYNC16(bdst + i * 4096u, bsrc + (size_t)i * 32 * BLKD);
            asm volatile("cp.async.commit_group;" ::: "memory");
            // LDG A(kt+1)
            const float* asrc = Ag + (size_t)(kt + 1) * BK;
            #pragma unroll
            for (int i = 0; i < 4; i++)
                ra[i] = *reinterpret_cast<const float4*>(asrc + (size_t)i * 32 * HIDDEN);
            asm volatile("cp.async.wait_group 1;" ::: "memory");
        } else {
            asm volatile("cp.async.wait_group 0;" ::: "memory");
        }
        __syncthreads();

        // ---- compute on buf: 4 k8-steps ----
        const uint32_t abase = sbase + buf;
        const uint32_t bbase = sbase + buf + ABYTES;
        #pragma unroll
        for (int ks = 0; ks < 4; ks++) {
            uint32_t aF[4][4], bF[4][2];
            #pragma unroll
            for (int mi = 0; mi < 4; mi++) {
                uint32_t off = (uint32_t)((wm0 + mi * 16 + a_rowadd) * 128 + a_colb + ks * 32);
                LDSM4(aF[mi][0], aF[mi][1], aF[mi][2], aF[mi][3], abase + SWZ(off));
            }
            #pragma unroll
            for (int p = 0; p < 2; p++) {
                uint32_t off = (uint32_t)((wn0 + p * 16 + b_rowadd) * 128 + b_colb + ks * 32);
                LDSM4(bF[2 * p][0], bF[2 * p][1], bF[2 * p + 1][0], bF[2 * p + 1][1],
                      bbase + SWZ(off));
            }
            #pragma unroll
            for (int mi = 0; mi < 4; mi++)
                #pragma unroll
                for (int nt = 0; nt < 4; nt++)
                    MMA_TF32(acc[mi][nt], aF[mi], bF[nt]);
        }
    }

    // ---- epilogue: direct float2 stores ----
    #pragma unroll
    for (int mi = 0; mi < 4; mi++) {
        const int grow = m0 + wm0 + mi * 16 + (l >> 2);
        #pragma unroll
        for (int nt = 0; nt < 4; nt++) {
            const int gcol = kb * BLKD + n0 + wn0 + nt * 8 + 2 * (l & 3);
            float2 v01 = make_float2(acc[mi][nt][0], acc[mi][nt][1]);
            float2 v23 = make_float2(acc[mi][nt][2], acc[mi][nt][3]);
            *reinterpret_cast<float2*>(out + (size_t)grow * HIDDEN + gcol) = v01;
            *reinterpret_cast<float2*>(out + (size_t)(grow + 8) * HIDDEN + gcol) = v23;
        }
    }
}

extern "C" void kernel_launch(void* const* d_in, const int* in_sizes, int n_in,
                              void* d_out, int out_size) {
    const float* x      = (const float*)d_in[0];
    const float* blocks = (const float*)d_in[1];
    float*       out    = (float*)d_out;

    const int M = in_sizes[0] / HIDDEN;  // 16384

    cudaFuncSetAttribute(tpt_mma_kernel,
                         cudaFuncAttributeMaxDynamicSharedMemorySize, SMEM_BYTES);

    dim3 gp(BLKD / 32, BLKD / 32, NB), bp(32, 8);
    prep_b_kernel<<<gp, bp>>>(blocks);

    dim3 gg(M / BM, BLKD / BN, NB), bg(NTH);
    tpt_mma_kernel<<<gg, bg, SMEM_BYTES>>>(x, out);
}